// round 16
// baseline (speedup 1.0000x reference)
#include <cuda_runtime.h>
#include <cuda_fp16.h>
#include <math.h>
#include <stdint.h>

#define BATCH   2
#define SEQ     2048
#define DMODEL  2048
#define NHEADS  16
#define DK      128
#define M_TOT   (BATCH*SEQ)   // 4096
#define KX      6144          // 3x expanded K for fp16 split GEMM

// ---------------- scratch ----------------
__device__ float  g_v  [M_TOT*DMODEL];
__device__ float  g_ao [M_TOT*DMODEL];
__device__ __half g_x3 [(size_t)M_TOT*KX];
__device__ __half g_ao3[(size_t)M_TOT*KX];
__device__ __half g_w3 [(size_t)4*DMODEL*KX];
__device__ __half g_qh [M_TOT*DMODEL];
__device__ __half g_ql [M_TOT*DMODEL];
__device__ __half g_kh [M_TOT*DMODEL];
__device__ __half g_kl [M_TOT*DMODEL];
__device__ __half g_vth[M_TOT*DMODEL];   // [b,h,d,s]
__device__ __half g_vtl[M_TOT*DMODEL];   // [b,h,d,s]

// ============================ PTX helpers ==================================
__device__ __forceinline__ uint32_t smem_u32(const void* p) {
    uint32_t a;
    asm("{ .reg .u64 t; cvta.to.shared.u64 t, %1; cvt.u32.u64 %0, t; }"
        : "=r"(a) : "l"(p));
    return a;
}
__device__ __forceinline__ void cp_async16(uint32_t dst, const void* src) {
    asm volatile("cp.async.cg.shared.global [%0], [%1], 16;"
                 :: "r"(dst), "l"(src) : "memory");
}
#define CP_COMMIT()  asm volatile("cp.async.commit_group;" ::: "memory")
#define CP_WAIT2()   asm volatile("cp.async.wait_group 2;" ::: "memory")
#define CP_WAIT1()   asm volatile("cp.async.wait_group 1;" ::: "memory")
#define CP_WAIT0()   asm volatile("cp.async.wait_group 0;" ::: "memory")

#define LDSM_X4(r, addr) \
    asm volatile("ldmatrix.sync.aligned.m8n8.x4.shared.b16 {%0,%1,%2,%3}, [%4];" \
        : "=r"((r)[0]), "=r"((r)[1]), "=r"((r)[2]), "=r"((r)[3]) : "r"(addr))

#define MMA16816(d, a, b) \
    asm volatile("mma.sync.aligned.m16n8k16.row.col.f32.f16.f16.f32 " \
        "{%0,%1,%2,%3}, {%4,%5,%6,%7}, {%8,%9}, {%0,%1,%2,%3};" \
        : "+f"((d)[0]), "+f"((d)[1]), "+f"((d)[2]), "+f"((d)[3]) \
        : "r"((a)[0]), "r"((a)[1]), "r"((a)[2]), "r"((a)[3]), \
          "r"((b)[0]), "r"((b)[1]))

// ===========================================================================
// Expansion: fp32 [rows,2048] -> fp16 [rows,6144].
//   act==1: per k emit (h,h,l)    act==0: per k emit (h,l,h)
// ===========================================================================
__global__ void conv_expand(const float* __restrict__ src,
                            __half* __restrict__ dst, int act)
{
    int p   = blockIdx.x * blockDim.x + threadIdx.x;
    int row = p >> 9;
    int kq  = (p & 511) * 4;

    float4 v = *(const float4*)(src + ((size_t)row << 11) + kq);
    float f[4] = {v.x, v.y, v.z, v.w};
    __half h[4], l[4];
#pragma unroll
    for (int i = 0; i < 4; ++i) {
        h[i] = __float2half_rn(f[i]);
        l[i] = __float2half_rn(f[i] - __half2float(h[i]));
    }

    __half o[12];
    if (act) {
#pragma unroll
        for (int i = 0; i < 4; ++i) { o[3*i] = h[i]; o[3*i+1] = h[i]; o[3*i+2] = l[i]; }
    } else {
#pragma unroll
        for (int i = 0; i < 4; ++i) { o[3*i] = h[i]; o[3*i+1] = l[i]; o[3*i+2] = h[i]; }
    }

    uint2* d = (uint2*)(dst + (size_t)row * KX + (size_t)kq * 3);
    const uint2* s2 = (const uint2*)o;
    d[0] = s2[0]; d[1] = s2[1]; d[2] = s2[2];
}

// all 4 weights in one launch; weight ordering (h,l,h)
__global__ void conv_expand_w(const float* __restrict__ w0, const float* __restrict__ w1,
                              const float* __restrict__ w2, const float* __restrict__ w3d,
                              __half* __restrict__ dst)
{
    int z = blockIdx.y;
    const float* src = (z == 0) ? w0 : (z == 1) ? w1 : (z == 2) ? w2 : w3d;
    int p   = blockIdx.x * blockDim.x + threadIdx.x;
    int row = p >> 9;
    int kq  = (p & 511) * 4;

    float4 v = *(const float4*)(src + ((size_t)row << 11) + kq);
    float f[4] = {v.x, v.y, v.z, v.w};
    __half h[4], l[4];
#pragma unroll
    for (int i = 0; i < 4; ++i) {
        h[i] = __float2half_rn(f[i]);
        l[i] = __float2half_rn(f[i] - __half2float(h[i]));
    }
    __half o[12];
#pragma unroll
    for (int i = 0; i < 4; ++i) { o[3*i] = h[i]; o[3*i+1] = l[i]; o[3*i+2] = h[i]; }

    uint2* d = (uint2*)(dst + (size_t)z * DMODEL * KX + (size_t)row * KX + (size_t)kq * 3);
    const uint2* s2 = (const uint2*)o;
    d[0] = s2[0]; d[1] = s2[1]; d[2] = s2[2];
}

// ===========================================================================
// Wide fp16 mma.sync GEMM: BM=128, BN=256, BK=64; 8 warps (2Mx4N),
// warp tile 64x64; 4-stage cp.async (192 KB smem, occ 1).
// mode 0: C = A@W^T + bias (fp32 out)
// mode 1: QKV fused epilogue — sel=n0>>11: 0-> rope+split to (qh,ql),
//         1-> rope+split to (kh,kl), 2-> plain fp32 v.
// ===========================================================================
#define GKT      (KX/64)     // 96
#define WSTAGES  4
#define WSTG_B   49152u      // A 16KB + B 32KB
#define WGEMM_SMEM (WSTAGES*WSTG_B)

__global__ __launch_bounds__(256, 1)
void gemm_mma_w(const __half* __restrict__ A3, const __half* __restrict__ W3,
                const float* __restrict__ bias, float* __restrict__ Cout,
                __half* __restrict__ QH, __half* __restrict__ QL,
                __half* __restrict__ KH, __half* __restrict__ KL,
                float* __restrict__ Vf, int mode)
{
    extern __shared__ unsigned char smraw[];
    const uint32_t sbase = smem_u32(smraw);

    const int tid  = threadIdx.x;
    const int lane = tid & 31, wid = tid >> 5;
    const int wm = wid & 1, wn = wid >> 1;          // 2 x 4 warp grid
    const int m0 = blockIdx.y * 128, n0 = blockIdx.x * 256;

    const int ldr = tid >> 3;          // 0..31
    const int ldc = tid & 7;
    const __half* agp = A3 + (size_t)(m0 + ldr) * KX + ldc * 8;
    const __half* wgp = W3 + (size_t)(n0 + ldr) * KX + ldc * 8;
    const uint32_t sw_off = (uint32_t)(ldr * 8 + (ldc ^ (ldr & 7))) * 16;

    float acc[4][8][4];
#pragma unroll
    for (int mi = 0; mi < 4; ++mi)
#pragma unroll
        for (int ni = 0; ni < 8; ++ni)
#pragma unroll
            for (int r = 0; r < 4; ++r) acc[mi][ni][r] = 0.f;

    const int arow = wm * 64 + (lane & 15);
    const int acb  = lane >> 4;
    const int brow0 = wn * 64 + (lane & 7) + ((lane >> 4) << 3);
    const int bcb  = (lane >> 3) & 1;

    auto load_stage = [&](int slot, int kt) {
        uint32_t s = sbase + (uint32_t)slot * WSTG_B;
        const __half* ag = agp + (size_t)kt * 64;
        const __half* wg = wgp + (size_t)kt * 64;
#pragma unroll
        for (int r4 = 0; r4 < 4; ++r4)          // A: 128 rows
            cp_async16(s + sw_off + (uint32_t)r4 * 4096,
                       ag + (size_t)r4 * 32 * KX);
#pragma unroll
        for (int r8 = 0; r8 < 8; ++r8)          // B: 256 rows
            cp_async16(s + 16384u + sw_off + (uint32_t)r8 * 4096,
                       wg + (size_t)r8 * 32 * KX);
    };

    auto compute_stage = [&](int slot) {
        uint32_t s  = sbase + (uint32_t)slot * WSTG_B;
        uint32_t sb = s + 16384u;
#pragma unroll
        for (int ks = 0; ks < 4; ++ks) {
            uint32_t a[4][4], b[8][2];
#pragma unroll
            for (int mi = 0; mi < 4; ++mi) {
                int row = arow + mi * 16;
                uint32_t addr = s + (uint32_t)(row * 8 + ((2*ks + acb) ^ (row & 7))) * 16;
                LDSM_X4(a[mi], addr);
            }
#pragma unroll
            for (int nj = 0; nj < 4; ++nj) {
                int row = brow0 + nj * 16;
                uint32_t addr = sb + (uint32_t)(row * 8 + ((2*ks + bcb) ^ (row & 7))) * 16;
                uint32_t r[4];
                LDSM_X4(r, addr);
                b[nj*2+0][0] = r[0]; b[nj*2+0][1] = r[1];
                b[nj*2+1][0] = r[2]; b[nj*2+1][1] = r[3];
            }
#pragma unroll
            for (int mi = 0; mi < 4; ++mi)
#pragma unroll
                for (int ni = 0; ni < 8; ++ni)
                    MMA16816(acc[mi][ni], a[mi], b[ni]);
        }
    };

    load_stage(0, 0); CP_COMMIT();
    load_stage(1, 1); CP_COMMIT();
    load_stage(2, 2); CP_COMMIT();

    for (int kt = 0; kt < GKT; ++kt) {
        CP_WAIT2();
        __syncthreads();
        int pf = kt + 3;
        if (pf < GKT) load_stage(pf & 3, pf);
        CP_COMMIT();                      // empty group at tail keeps count uniform
        compute_stage(kt & 3);
    }

    // ---------------- epilogue ----------------
    if (mode == 0) {
#pragma unroll
        for (int mi = 0; mi < 4; ++mi) {
            int row = m0 + wm * 64 + mi * 16 + (lane >> 2);
#pragma unroll
            for (int ni = 0; ni < 8; ++ni) {
                int col = n0 + wn * 64 + ni * 8 + (lane & 3) * 2;
                float b0 = __ldg(bias + col), b1 = __ldg(bias + col + 1);
                float2 v0 = {acc[mi][ni][0] + b0, acc[mi][ni][1] + b1};
                float2 v1 = {acc[mi][ni][2] + b0, acc[mi][ni][3] + b1};
                *(float2*)(Cout + (size_t) row      * DMODEL + col) = v0;
                *(float2*)(Cout + (size_t)(row + 8) * DMODEL + col) = v1;
            }
        }
    } else {
        const int sel = n0 >> 11;
        const int nc  = n0 & (DMODEL - 1);
        __half* H = (sel == 0) ? QH : KH;
        __half* L = (sel == 0) ? QL : KL;
#pragma unroll
        for (int mi = 0; mi < 4; ++mi) {
            int row = m0 + wm * 64 + mi * 16 + (lane >> 2);
#pragma unroll
            for (int ni = 0; ni < 8; ++ni) {
                int cg = nc + wn * 64 + ni * 8 + (lane & 3) * 2;
                float2 v0 = {acc[mi][ni][0], acc[mi][ni][1]};
                float2 v1 = {acc[mi][ni][2], acc[mi][ni][3]};
                if (sel == 2) {
                    *(float2*)(Vf + (size_t) row      * DMODEL + cg) = v0;
                    *(float2*)(Vf + (size_t)(row + 8) * DMODEL + cg) = v1;
                } else {
                    float freq = expf(-(float)(cg & 126) * 0.07195578415f);
                    float sn, cs;
                    // row: s = row & 2047
                    sincosf((float)(row & (SEQ-1)) * freq, &sn, &cs);
                    float r0 = v0.x*cs - v0.y*sn, r1 = v0.x*sn + v0.y*cs;
                    __half2 hh = __floats2half2_rn(r0, r1);
                    float2  hf = __half22float2(hh);
                    __half2 ll = __floats2half2_rn(r0 - hf.x, r1 - hf.y);
                    *(__half2*)(H + (size_t)row * DMODEL + cg) = hh;
                    *(__half2*)(L + (size_t)row * DMODEL + cg) = ll;
                    // row + 8
                    sincosf((float)((row + 8) & (SEQ-1)) * freq, &sn, &cs);
                    float t0 = v1.x*cs - v1.y*sn, t1 = v1.x*sn + v1.y*cs;
                    __half2 hh2 = __floats2half2_rn(t0, t1);
                    float2  hf2 = __half22float2(hh2);
                    __half2 ll2 = __floats2half2_rn(t0 - hf2.x, t1 - hf2.y);
                    *(__half2*)(H + (size_t)(row + 8) * DMODEL + cg) = hh2;
                    *(__half2*)(L + (size_t)(row + 8) * DMODEL + cg) = ll2;
                }
            }
        }
    }
}

// ---------------------------------------------------------------------------
// V transpose + split (unchanged, verified)
// ---------------------------------------------------------------------------
__global__ void vt_split(const float* __restrict__ v,
                         __half* __restrict__ vth, __half* __restrict__ vtl)
{
    __shared__ float sm[64][129];
    int s0 = blockIdx.x * 64;
    int bh = blockIdx.y;
    int b  = bh >> 4, h = bh & 15;
    const float* src = v + (size_t)(b*SEQ)*DMODEL + h*DK;

    for (int i = threadIdx.x; i < 64*32; i += 256) {
        int r = i >> 5, c4 = (i & 31) * 4;
        float4 vv = *(const float4*)(src + (size_t)(s0 + r) * DMODEL + c4);
        sm[r][c4] = vv.x; sm[r][c4+1] = vv.y; sm[r][c4+2] = vv.z; sm[r][c4+3] = vv.w;
    }
    __syncthreads();

    int d  = threadIdx.x >> 1;
    int j0 = (threadIdx.x & 1) * 32;
    size_t obase = ((size_t)bh * DK + d) * SEQ + s0 + j0;
#pragma unroll
    for (int jj = 0; jj < 32; jj += 8) {
        __half hh[8], ll[8];
#pragma unroll
        for (int u = 0; u < 8; ++u) {
            float f = sm[j0 + jj + u][d];
            __half x = __float2half_rn(f);
            hh[u] = x;
            ll[u] = __float2half_rn(f - __half2float(x));
        }
        *(uint4*)(vth + obase + jj) = *(uint4*)hh;
        *(uint4*)(vtl + obase + jj) = *(uint4*)ll;
    }
}

// ===========================================================================
// mma.sync causal flash attention (verified R14 version, unchanged)
// ===========================================================================
#define ABQ   128
#define ABKV  64
#define AQH_O 0u
#define AQL_O 32768u
#define AKV_O 65536u
#define AKV_STG 65536u
#define AKH_O 0u
#define AKL_O 16384u
#define AVH_O 32768u
#define AVL_O 49152u
#define ATTN_SMEM (65536u + 2u*65536u)

__global__ __launch_bounds__(256, 1)
void flash_attn_mma(const __half* __restrict__ qh, const __half* __restrict__ ql,
                    const __half* __restrict__ kh, const __half* __restrict__ kl,
                    const __half* __restrict__ vth, const __half* __restrict__ vtl,
                    float* __restrict__ Og)
{
    extern __shared__ unsigned char smraw[];
    const uint32_t sb = smem_u32(smraw);
    const int tid = threadIdx.x, lane = tid & 31, wid = tid >> 5;
    const int qblk = gridDim.x - 1 - blockIdx.x;
    const int q0 = qblk * ABQ;
    const int bh = blockIdx.y;
    const int b  = bh >> 4, h = bh & 15;
    const size_t qk_base = (size_t)(b*SEQ)*DMODEL + h*DK;
    const size_t vt_base = (size_t)bh * DK * SEQ;

    const int ntiles = q0 / ABKV + 2;
    const int g = lane >> 2, t4 = lane & 3;
    const int wq0 = q0 + wid * 16;

    {   // Q tiles
        int c  = tid & 15;
        int r0 = tid >> 4;
#pragma unroll
        for (int rr = 0; rr < 8; ++rr) {
            int row = r0 + rr * 16;
            uint32_t dst = (uint32_t)(row * 16 + (c ^ (row & 7))) * 16;
            cp_async16(sb + AQH_O + dst,
                       qh + qk_base + (size_t)(q0 + row) * DMODEL + c * 8);
            cp_async16(sb + AQL_O + dst,
                       ql + qk_base + (size_t)(q0 + row) * DMODEL + c * 8);
        }
    }
    auto load_kv = [&](int st, int tl) {
        uint32_t s = sb + AKV_O + (uint32_t)st * AKV_STG;
        int k0 = tl * ABKV;
        {
            int c  = tid & 15;
            int r0 = tid >> 4;
#pragma unroll
            for (int rr = 0; rr < 4; ++rr) {
                int row = r0 + rr * 16;
                uint32_t dst = (uint32_t)(row * 16 + (c ^ (row & 7))) * 16;
                cp_async16(s + AKH_O + dst,
                           kh + qk_base + (size_t)(k0 + row) * DMODEL + c * 8);
                cp_async16(s + AKL_O + dst,
                           kl + qk_base + (size_t)(k0 + row) * DMODEL + c * 8);
            }
        }
        {
            int c  = tid & 7;
            int r0 = tid >> 3;
#pragma unroll
            for (int rr = 0; rr < 4; ++rr) {
                int row = r0 + rr * 32;
                uint32_t dst = (uint32_t)(row * 8 + (c ^ (row & 7))) * 16;
                cp_async16(s + AVH_O + dst,
                           vth + vt_base + (size_t)row * SEQ + k0 + c * 8);
                cp_async16(s + AVL_O + dst,
                           vtl + vt_base + (size_t)row * SEQ + k0 + c * 8);
            }
        }
    };

    load_kv(0, 0); CP_COMMIT();

    float o[16][4];
#pragma unroll
    for (int nt = 0; nt < 16; ++nt)
#pragma unroll
        for (int r = 0; r < 4; ++r) o[nt][r] = 0.f;
    float m0 = -1e30f, m1 = -1e30f, den0 = 0.f, den1 = 0.f;
    const float scale = 0.08838834764831845f;

    for (int tl = 0; tl < ntiles; ++tl) {
        int k0 = tl * ABKV;
        if (tl + 1 < ntiles) { load_kv((tl + 1) & 1, tl + 1); CP_COMMIT(); CP_WAIT1(); }
        else                 { CP_WAIT0(); }
        __syncthreads();

        uint32_t st = sb + AKV_O + (uint32_t)(tl & 1) * AKV_STG;

        if (k0 <= wq0 + 15) {
            float s4[8][4];
#pragma unroll
            for (int nt = 0; nt < 8; ++nt)
#pragma unroll
                for (int r = 0; r < 4; ++r) s4[nt][r] = 0.f;

            const int arow = wid * 16 + (lane & 15);
            const int brow0 = (lane & 7) + ((lane >> 4) << 3);
            const int bcbit = (lane >> 3) & 1;
#pragma unroll
            for (int ks = 0; ks < 8; ++ks) {
                int ach = 2 * ks + (lane >> 4);
                uint32_t qoff = (uint32_t)(arow * 16 + (ach ^ (arow & 7))) * 16;
                uint32_t aH[4], aL[4];
                LDSM_X4(aH, sb + AQH_O + qoff);
                LDSM_X4(aL, sb + AQL_O + qoff);
#pragma unroll
                for (int nj = 0; nj < 4; ++nj) {
                    int brow = brow0 + nj * 16;
                    int bch  = 2 * ks + bcbit;
                    uint32_t koff = (uint32_t)(brow * 16 + (bch ^ (brow & 7))) * 16;
                    uint32_t rH[4], rL[4];
                    LDSM_X4(rH, st + AKH_O + koff);
                    LDSM_X4(rL, st + AKL_O + koff);
                    uint32_t bH0[2] = {rH[0], rH[1]}, bH1[2] = {rH[2], rH[3]};
                    uint32_t bL0[2] = {rL[0], rL[1]}, bL1[2] = {rL[2], rL[3]};
                    MMA16816(s4[2*nj],   aH, bH0);
                    MMA16816(s4[2*nj+1], aH, bH1);
                    MMA16816(s4[2*nj],   aH, bL0);
                    MMA16816(s4[2*nj+1], aH, bL1);
                    MMA16816(s4[2*nj],   aL, bH0);
                    MMA16816(s4[2*nj+1], aL, bH1);
                }
            }

            const bool domask = (k0 + ABKV - 1 > wq0);
            const int r0g = wq0 + g, r1g = wq0 + 8 + g;
#pragma unroll
            for (int nt = 0; nt < 8; ++nt) {
#pragma unroll
                for (int r = 0; r < 4; ++r) s4[nt][r] *= scale;
                if (domask) {
                    int c0 = k0 + nt * 8 + 2 * t4;
                    if (c0     > r0g) s4[nt][0] = -1e30f;
                    if (c0 + 1 > r0g) s4[nt][1] = -1e30f;
                    if (c0     > r1g) s4[nt][2] = -1e30f;
                    if (c0 + 1 > r1g) s4[nt][3] = -1e30f;
                }
            }

            float mx0 = -1e30f, mx1 = -1e30f;
#pragma unroll
            for (int nt = 0; nt < 8; ++nt) {
                mx0 = fmaxf(mx0, fmaxf(s4[nt][0], s4[nt][1]));
                mx1 = fmaxf(mx1, fmaxf(s4[nt][2], s4[nt][3]));
            }
            mx0 = fmaxf(mx0, __shfl_xor_sync(0xffffffffu, mx0, 1));
            mx0 = fmaxf(mx0, __shfl_xor_sync(0xffffffffu, mx0, 2));
            mx1 = fmaxf(mx1, __shfl_xor_sync(0xffffffffu, mx1, 1));
            mx1 = fmaxf(mx1, __shfl_xor_sync(0xffffffffu, mx1, 2));
            float mn0 = fmaxf(m0, mx0), mn1 = fmaxf(m1, mx1);
            float al0 = __expf(m0 - mn0), al1 = __expf(m1 - mn1);
            m0 = mn0; m1 = mn1;

            float sum0 = 0.f, sum1 = 0.f;
            uint32_t phA[8], phB[8], plA[8], plB[8];
#pragma unroll
            for (int nt = 0; nt < 8; ++nt) {
                float e0 = __expf(s4[nt][0] - mn0), e1 = __expf(s4[nt][1] - mn0);
                float e2 = __expf(s4[nt][2] - mn1), e3 = __expf(s4[nt][3] - mn1);
                sum0 += e0 + e1; sum1 += e2 + e3;
                __half2 h0 = __floats2half2_rn(e0, e1);
                __half2 h1 = __floats2half2_rn(e2, e3);
                float2 f0 = __half22float2(h0), f1 = __half22float2(h1);
                __half2 q0h = __floats2half2_rn(e0 - f0.x, e1 - f0.y);
                __half2 q1h = __floats2half2_rn(e2 - f1.x, e3 - f1.y);
                phA[nt] = *(uint32_t*)&h0;  phB[nt] = *(uint32_t*)&h1;
                plA[nt] = *(uint32_t*)&q0h; plB[nt] = *(uint32_t*)&q1h;
            }
            sum0 += __shfl_xor_sync(0xffffffffu, sum0, 1);
            sum0 += __shfl_xor_sync(0xffffffffu, sum0, 2);
            sum1 += __shfl_xor_sync(0xffffffffu, sum1, 1);
            sum1 += __shfl_xor_sync(0xffffffffu, sum1, 2);
            den0 = den0 * al0 + sum0;
            den1 = den1 * al1 + sum1;

#pragma unroll
            for (int nt = 0; nt < 16; ++nt) {
                o[nt][0] *= al0; o[nt][1] *= al0;
                o[nt][2] *= al1; o[nt][3] *= al1;
            }

#pragma unroll
            for (int ks = 0; ks < 4; ++ks) {
                uint32_t aH[4] = {phA[2*ks], phB[2*ks], phA[2*ks+1], phB[2*ks+1]};
                uint32_t aL[4] = {plA[2*ks], plB[2*ks], plA[2*ks+1], plB[2*ks+1]};
#pragma unroll
                for (int nj = 0; nj < 8; ++nj) {
                    int brow = brow0 + nj * 16;
                    int bch  = 2 * ks + bcbit;
                    uint32_t voff = (uint32_t)(brow * 8 + (bch ^ (brow & 7))) * 16;
                    uint32_t rH[4], rL[4];
                    LDSM_X4(rH, st + AVH_O + voff);
                    LDSM_X4(rL, st + AVL_O + voff);
                    uint32_t bH0[2] = {rH[0], rH[1]}, bH1[2] = {rH[2], rH[3]};
                    uint32_t bL0[2] = {rL[0], rL[1]}, bL1[2] = {rL[2], rL[3]};
                    MMA16816(o[2*nj],   aH, bH0);
                    MMA16816(o[2*nj+1], aH, bH1);
                    MMA16816(o[2*nj],   aH, bL0);
                    MMA16816(o[2*nj+1], aH, bL1);
                    MMA16816(o[2*nj],   aL, bH0);
                    MMA16816(o[2*nj+1], aL, bH1);
                }
            }
        }
        __syncthreads();
    }

    float inv0 = 1.f / den0, inv1 = 1.f / den1;
    int row0 = wq0 + g;
    float* O0 = Og + (size_t)(b*SEQ + row0) * DMODEL + h * DK;
    float* O1 = O0 + (size_t)8 * DMODEL;
#pragma unroll
    for (int nt = 0; nt < 16; ++nt) {
        int col = nt * 8 + 2 * t4;
        float2 v0 = {o[nt][0] * inv0, o[nt][1] * inv0};
        float2 v1 = {o[nt][2] * inv1, o[nt][3] * inv1};
        *(float2*)(O0 + col) = v0;
        *(float2*)(O1 + col) = v1;
    }
}

// ---------------------------------------------------------------------------
extern "C" void kernel_launch(void* const* d_in, const int* in_sizes, int n_in,
                              void* d_out, int out_size)
{
    (void)in_sizes; (void)n_in; (void)out_size;
    const float* x  = (const float*)d_in[0];
    const float* wq = (const float*)d_in[1];
    const float* wk = (const float*)d_in[2];
    const float* wv = (const float*)d_in[3];
    const float* wo = (const float*)d_in[4];
    const float* bo = (const float*)d_in[5];
    float* out = (float*)d_out;

    float *v, *ao;
    __half *x3, *ao3, *w3, *qh, *ql, *kh, *kl, *vth, *vtl;
    cudaGetSymbolAddress((void**)&v,   g_v);
    cudaGetSymbolAddress((void**)&ao,  g_ao);
    cudaGetSymbolAddress((void**)&x3,  g_x3);
    cudaGetSymbolAddress((void**)&ao3, g_ao3);
    cudaGetSymbolAddress((void**)&w3,  g_w3);
    cudaGetSymbolAddress((void**)&qh,  g_qh);
    cudaGetSymbolAddress((void**)&ql,  g_ql);
    cudaGetSymbolAddress((void**)&kh,  g_kh);
    cudaGetSymbolAddress((void**)&kl,  g_kl);
    cudaGetSymbolAddress((void**)&vth, g_vth);
    cudaGetSymbolAddress((void**)&vtl, g_vtl);

    const size_t W3SZ = (size_t)DMODEL * KX;

    conv_expand<<<(M_TOT*512)/256, 256>>>(x, x3, 1);
    conv_expand_w<<<dim3((DMODEL*512)/256, 4), 256>>>(wq, wk, wv, wo, w3);

    cudaFuncSetAttribute(gemm_mma_w, cudaFuncAttributeMaxDynamicSharedMemorySize,
                         (int)WGEMM_SMEM);
    // fused QKV with rope+split epilogue: N = 6144
    dim3 gqkv(3*DMODEL/256, M_TOT/128);   // (24, 32)
    gemm_mma_w<<<gqkv, 256, WGEMM_SMEM>>>(x3, w3, nullptr, nullptr,
                                          qh, ql, kh, kl, v, 1);

    vt_split<<<dim3(SEQ/64, BATCH*NHEADS), 256>>>(v, vth, vtl);

    cudaFuncSetAttribute(flash_attn_mma, cudaFuncAttributeMaxDynamicSharedMemorySize,
                         (int)ATTN_SMEM);
    dim3 agrid(SEQ/ABQ, BATCH*NHEADS);   // (16, 32)
    flash_attn_mma<<<agrid, 256, ATTN_SMEM>>>(qh, ql, kh, kl, vth, vtl, ao);

    conv_expand<<<(M_TOT*512)/256, 256>>>(ao, ao3, 1);
    dim3 gout(DMODEL/256, M_TOT/128);     // (8, 32)
    gemm_mma_w<<<gout, 256, WGEMM_SMEM>>>(ao3, w3 + 3*W3SZ, bo, out,
                                          nullptr, nullptr, nullptr, nullptr,
                                          nullptr, 0);
}

// round 17
// speedup vs baseline: 1.0890x; 1.0890x over previous
#include <cuda_runtime.h>
#include <cuda_fp16.h>
#include <math.h>
#include <stdint.h>

#define BATCH   2
#define SEQ     2048
#define DMODEL  2048
#define NHEADS  16
#define DK      128
#define M_TOT   (BATCH*SEQ)   // 4096
#define KX      6144          // 3x expanded K for fp16 split GEMM

// ---------------- scratch ----------------
__device__ float  g_v  [M_TOT*DMODEL];
__device__ float  g_ao [M_TOT*DMODEL];
__device__ __half g_x3 [(size_t)M_TOT*KX];
__device__ __half g_ao3[(size_t)M_TOT*KX];
__device__ __half g_w3 [(size_t)4*DMODEL*KX];
__device__ __half g_qh [M_TOT*DMODEL];
__device__ __half g_ql [M_TOT*DMODEL];
__device__ __half g_kh [M_TOT*DMODEL];
__device__ __half g_kl [M_TOT*DMODEL];
__device__ __half g_vth[M_TOT*DMODEL];   // [b,h,d,s]
__device__ __half g_vtl[M_TOT*DMODEL];   // [b,h,d,s]

// ============================ PTX helpers ==================================
__device__ __forceinline__ uint32_t smem_u32(const void* p) {
    uint32_t a;
    asm("{ .reg .u64 t; cvta.to.shared.u64 t, %1; cvt.u32.u64 %0, t; }"
        : "=r"(a) : "l"(p));
    return a;
}
__device__ __forceinline__ void cp_async16(uint32_t dst, const void* src) {
    asm volatile("cp.async.cg.shared.global [%0], [%1], 16;"
                 :: "r"(dst), "l"(src) : "memory");
}
#define CP_COMMIT()  asm volatile("cp.async.commit_group;" ::: "memory")
#define CP_WAIT1()   asm volatile("cp.async.wait_group 1;" ::: "memory")
#define CP_WAIT0()   asm volatile("cp.async.wait_group 0;" ::: "memory")

#define LDSM_X4(r, addr) \
    asm volatile("ldmatrix.sync.aligned.m8n8.x4.shared.b16 {%0,%1,%2,%3}, [%4];" \
        : "=r"((r)[0]), "=r"((r)[1]), "=r"((r)[2]), "=r"((r)[3]) : "r"(addr))

#define MMA16816(d, a, b) \
    asm volatile("mma.sync.aligned.m16n8k16.row.col.f32.f16.f16.f32 " \
        "{%0,%1,%2,%3}, {%4,%5,%6,%7}, {%8,%9}, {%0,%1,%2,%3};" \
        : "+f"((d)[0]), "+f"((d)[1]), "+f"((d)[2]), "+f"((d)[3]) \
        : "r"((a)[0]), "r"((a)[1]), "r"((a)[2]), "r"((a)[3]), \
          "r"((b)[0]), "r"((b)[1]))

// ===========================================================================
// Expansion: fp32 [rows,2048] -> fp16 [rows,6144].
//   act==1: per k emit (h,h,l)    act==0: per k emit (h,l,h)
// ===========================================================================
__global__ void conv_expand(const float* __restrict__ src,
                            __half* __restrict__ dst, int act)
{
    int p   = blockIdx.x * blockDim.x + threadIdx.x;
    int row = p >> 9;
    int kq  = (p & 511) * 4;

    float4 v = *(const float4*)(src + ((size_t)row << 11) + kq);
    float f[4] = {v.x, v.y, v.z, v.w};
    __half h[4], l[4];
#pragma unroll
    for (int i = 0; i < 4; ++i) {
        h[i] = __float2half_rn(f[i]);
        l[i] = __float2half_rn(f[i] - __half2float(h[i]));
    }

    __half o[12];
    if (act) {
#pragma unroll
        for (int i = 0; i < 4; ++i) { o[3*i] = h[i]; o[3*i+1] = h[i]; o[3*i+2] = l[i]; }
    } else {
#pragma unroll
        for (int i = 0; i < 4; ++i) { o[3*i] = h[i]; o[3*i+1] = l[i]; o[3*i+2] = h[i]; }
    }

    uint2* d = (uint2*)(dst + (size_t)row * KX + (size_t)kq * 3);
    const uint2* s2 = (const uint2*)o;
    d[0] = s2[0]; d[1] = s2[1]; d[2] = s2[2];
}

// all 4 weights in one launch; weight ordering (h,l,h)
__global__ void conv_expand_w(const float* __restrict__ w0, const float* __restrict__ w1,
                              const float* __restrict__ w2, const float* __restrict__ w3d,
                              __half* __restrict__ dst)
{
    int z = blockIdx.y;
    const float* src = (z == 0) ? w0 : (z == 1) ? w1 : (z == 2) ? w2 : w3d;
    int p   = blockIdx.x * blockDim.x + threadIdx.x;
    int row = p >> 9;
    int kq  = (p & 511) * 4;

    float4 v = *(const float4*)(src + ((size_t)row << 11) + kq);
    float f[4] = {v.x, v.y, v.z, v.w};
    __half h[4], l[4];
#pragma unroll
    for (int i = 0; i < 4; ++i) {
        h[i] = __float2half_rn(f[i]);
        l[i] = __float2half_rn(f[i] - __half2float(h[i]));
    }
    __half o[12];
#pragma unroll
    for (int i = 0; i < 4; ++i) { o[3*i] = h[i]; o[3*i+1] = l[i]; o[3*i+2] = h[i]; }

    uint2* d = (uint2*)(dst + (size_t)z * DMODEL * KX + (size_t)row * KX + (size_t)kq * 3);
    const uint2* s2 = (const uint2*)o;
    d[0] = s2[0]; d[1] = s2[1]; d[2] = s2[2];
}

// ===========================================================================
// fp16 mma.sync GEMM — verified R14 config: BM=BN=128, BK=64, 8 warps (2x4),
// warp tile 64x32, 3-stage cp.async, occ 2.
// mode 0: C = A@W^T + bias (fp32 out)
// mode 1: QKV fused epilogue — sel = n0>>11: 0 -> rope+split (qh,ql),
//         1 -> rope+split (kh,kl), 2 -> plain fp32 v.
// ===========================================================================
#define GKT      (KX/64)     // 96
#define STAGES   3
#define STG_B    32768u
#define GEMM_SMEM (STAGES*STG_B)

__global__ __launch_bounds__(256, 2)
void gemm_mma(const __half* __restrict__ A3, const __half* __restrict__ W3,
              const float* __restrict__ bias, float* __restrict__ Cout,
              __half* __restrict__ QH, __half* __restrict__ QL,
              __half* __restrict__ KH, __half* __restrict__ KL,
              float* __restrict__ Vf, int mode)
{
    extern __shared__ unsigned char smraw[];
    const uint32_t sbase = smem_u32(smraw);

    const int tid  = threadIdx.x;
    const int lane = tid & 31, wid = tid >> 5;
    const int wm = wid & 1, wn = wid >> 1;
    const int m0 = blockIdx.y * 128, n0 = blockIdx.x * 128;

    const int ldr = tid >> 3;
    const int ldc = tid & 7;
    const __half* agp = A3 + (size_t)(m0 + ldr) * KX + ldc * 8;
    const __half* wgp = W3 + (size_t)(n0 + ldr) * KX + ldc * 8;
    const uint32_t sw_off = (uint32_t)(ldr * 8 + (ldc ^ (ldr & 7))) * 16;

    float acc[4][4][4];
#pragma unroll
    for (int mi = 0; mi < 4; ++mi)
#pragma unroll
        for (int ni = 0; ni < 4; ++ni)
#pragma unroll
            for (int r = 0; r < 4; ++r) acc[mi][ni][r] = 0.f;

    const int arow = wm * 64 + (lane & 15);
    const int acb  = lane >> 4;
    const int brow = wn * 32 + (lane & 7) + ((lane >> 4) << 3);
    const int bcb  = (lane >> 3) & 1;

    auto load_stage = [&](int slot, int kt) {
        uint32_t s = sbase + (uint32_t)slot * STG_B;
        const __half* ag = agp + (size_t)kt * 64;
        const __half* wg = wgp + (size_t)kt * 64;
#pragma unroll
        for (int r4 = 0; r4 < 4; ++r4) {
            uint32_t o = sw_off + (uint32_t)r4 * 32 * 128;
            cp_async16(s + o,          ag + (size_t)r4 * 32 * KX);
            cp_async16(s + 16384u + o, wg + (size_t)r4 * 32 * KX);
        }
    };

    auto compute_stage = [&](int slot) {
        uint32_t s  = sbase + (uint32_t)slot * STG_B;
        uint32_t sb = s + 16384u;
#pragma unroll
        for (int ks = 0; ks < 4; ++ks) {
            uint32_t a[4][4], b[4][2];
#pragma unroll
            for (int mi = 0; mi < 4; ++mi) {
                int row = arow + mi * 16;
                uint32_t addr = s + (uint32_t)(row * 8 + ((2*ks + acb) ^ (row & 7))) * 16;
                LDSM_X4(a[mi], addr);
            }
#pragma unroll
            for (int nj = 0; nj < 2; ++nj) {
                int row = brow + nj * 16;
                uint32_t addr = sb + (uint32_t)(row * 8 + ((2*ks + bcb) ^ (row & 7))) * 16;
                uint32_t r[4];
                LDSM_X4(r, addr);
                b[nj*2+0][0] = r[0]; b[nj*2+0][1] = r[1];
                b[nj*2+1][0] = r[2]; b[nj*2+1][1] = r[3];
            }
#pragma unroll
            for (int mi = 0; mi < 4; ++mi)
#pragma unroll
                for (int ni = 0; ni < 4; ++ni)
                    MMA16816(acc[mi][ni], a[mi], b[ni]);
        }
    };

    load_stage(0, 0); CP_COMMIT();
    load_stage(1, 1); CP_COMMIT();

    for (int kt = 0; kt < GKT; ++kt) {
        CP_WAIT1();
        __syncthreads();
        int pf = kt + STAGES - 1;
        if (pf < GKT) { load_stage(pf % STAGES, pf); CP_COMMIT(); }
        compute_stage(kt % STAGES);
    }

    // ---------------- epilogue ----------------
    if (mode == 0) {
#pragma unroll
        for (int mi = 0; mi < 4; ++mi) {
            int row = m0 + wm * 64 + mi * 16 + (lane >> 2);
#pragma unroll
            for (int ni = 0; ni < 4; ++ni) {
                int col = n0 + wn * 32 + ni * 8 + (lane & 3) * 2;
                float b0 = __ldg(bias + col), b1 = __ldg(bias + col + 1);
                float2 v0 = {acc[mi][ni][0] + b0, acc[mi][ni][1] + b1};
                float2 v1 = {acc[mi][ni][2] + b0, acc[mi][ni][3] + b1};
                *(float2*)(Cout + (size_t) row      * DMODEL + col) = v0;
                *(float2*)(Cout + (size_t)(row + 8) * DMODEL + col) = v1;
            }
        }
    } else {
        const int sel = n0 >> 11;
        const int nc  = n0 & (DMODEL - 1);
        __half* H = (sel == 0) ? QH : KH;
        __half* L = (sel == 0) ? QL : KL;
#pragma unroll
        for (int mi = 0; mi < 4; ++mi) {
            int row = m0 + wm * 64 + mi * 16 + (lane >> 2);
#pragma unroll
            for (int ni = 0; ni < 4; ++ni) {
                int cg = nc + wn * 32 + ni * 8 + (lane & 3) * 2;
                float2 v0 = {acc[mi][ni][0], acc[mi][ni][1]};
                float2 v1 = {acc[mi][ni][2], acc[mi][ni][3]};
                if (sel == 2) {
                    *(float2*)(Vf + (size_t) row      * DMODEL + cg) = v0;
                    *(float2*)(Vf + (size_t)(row + 8) * DMODEL + cg) = v1;
                } else {
                    float freq = expf(-(float)(cg & 126) * 0.07195578415f);
                    float sn, cs;
                    sincosf((float)(row & (SEQ-1)) * freq, &sn, &cs);
                    float r0 = v0.x*cs - v0.y*sn, r1 = v0.x*sn + v0.y*cs;
                    __half2 hh = __floats2half2_rn(r0, r1);
                    float2  hf = __half22float2(hh);
                    __half2 ll = __floats2half2_rn(r0 - hf.x, r1 - hf.y);
                    *(__half2*)(H + (size_t)row * DMODEL + cg) = hh;
                    *(__half2*)(L + (size_t)row * DMODEL + cg) = ll;
                    sincosf((float)((row + 8) & (SEQ-1)) * freq, &sn, &cs);
                    float t0 = v1.x*cs - v1.y*sn, t1 = v1.x*sn + v1.y*cs;
                    __half2 hh2 = __floats2half2_rn(t0, t1);
                    float2  hf2 = __half22float2(hh2);
                    __half2 ll2 = __floats2half2_rn(t0 - hf2.x, t1 - hf2.y);
                    *(__half2*)(H + (size_t)(row + 8) * DMODEL + cg) = hh2;
                    *(__half2*)(L + (size_t)(row + 8) * DMODEL + cg) = ll2;
                }
            }
        }
    }
}

// ---------------------------------------------------------------------------
// V transpose + split (unchanged, verified)
// ---------------------------------------------------------------------------
__global__ void vt_split(const float* __restrict__ v,
                         __half* __restrict__ vth, __half* __restrict__ vtl)
{
    __shared__ float sm[64][129];
    int s0 = blockIdx.x * 64;
    int bh = blockIdx.y;
    int b  = bh >> 4, h = bh & 15;
    const float* src = v + (size_t)(b*SEQ)*DMODEL + h*DK;

    for (int i = threadIdx.x; i < 64*32; i += 256) {
        int r = i >> 5, c4 = (i & 31) * 4;
        float4 vv = *(const float4*)(src + (size_t)(s0 + r) * DMODEL + c4);
        sm[r][c4] = vv.x; sm[r][c4+1] = vv.y; sm[r][c4+2] = vv.z; sm[r][c4+3] = vv.w;
    }
    __syncthreads();

    int d  = threadIdx.x >> 1;
    int j0 = (threadIdx.x & 1) * 32;
    size_t obase = ((size_t)bh * DK + d) * SEQ + s0 + j0;
#pragma unroll
    for (int jj = 0; jj < 32; jj += 8) {
        __half hh[8], ll[8];
#pragma unroll
        for (int u = 0; u < 8; ++u) {
            float f = sm[j0 + jj + u][d];
            __half x = __float2half_rn(f);
            hh[u] = x;
            ll[u] = __float2half_rn(f - __half2float(x));
        }
        *(uint4*)(vth + obase + jj) = *(uint4*)hh;
        *(uint4*)(vtl + obase + jj) = *(uint4*)ll;
    }
}

// ===========================================================================
// mma.sync causal flash attention (verified R14 version, unchanged)
// ===========================================================================
#define ABQ   128
#define ABKV  64
#define AQH_O 0u
#define AQL_O 32768u
#define AKV_O 65536u
#define AKV_STG 65536u
#define AKH_O 0u
#define AKL_O 16384u
#define AVH_O 32768u
#define AVL_O 49152u
#define ATTN_SMEM (65536u + 2u*65536u)

__global__ __launch_bounds__(256, 1)
void flash_attn_mma(const __half* __restrict__ qh, const __half* __restrict__ ql,
                    const __half* __restrict__ kh, const __half* __restrict__ kl,
                    const __half* __restrict__ vth, const __half* __restrict__ vtl,
                    float* __restrict__ Og)
{
    extern __shared__ unsigned char smraw[];
    const uint32_t sb = smem_u32(smraw);
    const int tid = threadIdx.x, lane = tid & 31, wid = tid >> 5;
    const int qblk = gridDim.x - 1 - blockIdx.x;
    const int q0 = qblk * ABQ;
    const int bh = blockIdx.y;
    const int b  = bh >> 4, h = bh & 15;
    const size_t qk_base = (size_t)(b*SEQ)*DMODEL + h*DK;
    const size_t vt_base = (size_t)bh * DK * SEQ;

    const int ntiles = q0 / ABKV + 2;
    const int g = lane >> 2, t4 = lane & 3;
    const int wq0 = q0 + wid * 16;

    {   // Q tiles
        int c  = tid & 15;
        int r0 = tid >> 4;
#pragma unroll
        for (int rr = 0; rr < 8; ++rr) {
            int row = r0 + rr * 16;
            uint32_t dst = (uint32_t)(row * 16 + (c ^ (row & 7))) * 16;
            cp_async16(sb + AQH_O + dst,
                       qh + qk_base + (size_t)(q0 + row) * DMODEL + c * 8);
            cp_async16(sb + AQL_O + dst,
                       ql + qk_base + (size_t)(q0 + row) * DMODEL + c * 8);
        }
    }
    auto load_kv = [&](int st, int tl) {
        uint32_t s = sb + AKV_O + (uint32_t)st * AKV_STG;
        int k0 = tl * ABKV;
        {
            int c  = tid & 15;
            int r0 = tid >> 4;
#pragma unroll
            for (int rr = 0; rr < 4; ++rr) {
                int row = r0 + rr * 16;
                uint32_t dst = (uint32_t)(row * 16 + (c ^ (row & 7))) * 16;
                cp_async16(s + AKH_O + dst,
                           kh + qk_base + (size_t)(k0 + row) * DMODEL + c * 8);
                cp_async16(s + AKL_O + dst,
                           kl + qk_base + (size_t)(k0 + row) * DMODEL + c * 8);
            }
        }
        {
            int c  = tid & 7;
            int r0 = tid >> 3;
#pragma unroll
            for (int rr = 0; rr < 4; ++rr) {
                int row = r0 + rr * 32;
                uint32_t dst = (uint32_t)(row * 8 + (c ^ (row & 7))) * 16;
                cp_async16(s + AVH_O + dst,
                           vth + vt_base + (size_t)row * SEQ + k0 + c * 8);
                cp_async16(s + AVL_O + dst,
                           vtl + vt_base + (size_t)row * SEQ + k0 + c * 8);
            }
        }
    };

    load_kv(0, 0); CP_COMMIT();

    float o[16][4];
#pragma unroll
    for (int nt = 0; nt < 16; ++nt)
#pragma unroll
        for (int r = 0; r < 4; ++r) o[nt][r] = 0.f;
    float m0 = -1e30f, m1 = -1e30f, den0 = 0.f, den1 = 0.f;
    const float scale = 0.08838834764831845f;

    for (int tl = 0; tl < ntiles; ++tl) {
        int k0 = tl * ABKV;
        if (tl + 1 < ntiles) { load_kv((tl + 1) & 1, tl + 1); CP_COMMIT(); CP_WAIT1(); }
        else                 { CP_WAIT0(); }
        __syncthreads();

        uint32_t st = sb + AKV_O + (uint32_t)(tl & 1) * AKV_STG;

        if (k0 <= wq0 + 15) {
            float s4[8][4];
#pragma unroll
            for (int nt = 0; nt < 8; ++nt)
#pragma unroll
                for (int r = 0; r < 4; ++r) s4[nt][r] = 0.f;

            const int arow = wid * 16 + (lane & 15);
            const int brow0 = (lane & 7) + ((lane >> 4) << 3);
            const int bcbit = (lane >> 3) & 1;
#pragma unroll
            for (int ks = 0; ks < 8; ++ks) {
                int ach = 2 * ks + (lane >> 4);
                uint32_t qoff = (uint32_t)(arow * 16 + (ach ^ (arow & 7))) * 16;
                uint32_t aH[4], aL[4];
                LDSM_X4(aH, sb + AQH_O + qoff);
                LDSM_X4(aL, sb + AQL_O + qoff);
#pragma unroll
                for (int nj = 0; nj < 4; ++nj) {
                    int brow = brow0 + nj * 16;
                    int bch  = 2 * ks + bcbit;
                    uint32_t koff = (uint32_t)(brow * 16 + (bch ^ (brow & 7))) * 16;
                    uint32_t rH[4], rL[4];
                    LDSM_X4(rH, st + AKH_O + koff);
                    LDSM_X4(rL, st + AKL_O + koff);
                    uint32_t bH0[2] = {rH[0], rH[1]}, bH1[2] = {rH[2], rH[3]};
                    uint32_t bL0[2] = {rL[0], rL[1]}, bL1[2] = {rL[2], rL[3]};
                    MMA16816(s4[2*nj],   aH, bH0);
                    MMA16816(s4[2*nj+1], aH, bH1);
                    MMA16816(s4[2*nj],   aH, bL0);
                    MMA16816(s4[2*nj+1], aH, bL1);
                    MMA16816(s4[2*nj],   aL, bH0);
                    MMA16816(s4[2*nj+1], aL, bH1);
                }
            }

            const bool domask = (k0 + ABKV - 1 > wq0);
            const int r0g = wq0 + g, r1g = wq0 + 8 + g;
#pragma unroll
            for (int nt = 0; nt < 8; ++nt) {
#pragma unroll
                for (int r = 0; r < 4; ++r) s4[nt][r] *= scale;
                if (domask) {
                    int c0 = k0 + nt * 8 + 2 * t4;
                    if (c0     > r0g) s4[nt][0] = -1e30f;
                    if (c0 + 1 > r0g) s4[nt][1] = -1e30f;
                    if (c0     > r1g) s4[nt][2] = -1e30f;
                    if (c0 + 1 > r1g) s4[nt][3] = -1e30f;
                }
            }

            float mx0 = -1e30f, mx1 = -1e30f;
#pragma unroll
            for (int nt = 0; nt < 8; ++nt) {
                mx0 = fmaxf(mx0, fmaxf(s4[nt][0], s4[nt][1]));
                mx1 = fmaxf(mx1, fmaxf(s4[nt][2], s4[nt][3]));
            }
            mx0 = fmaxf(mx0, __shfl_xor_sync(0xffffffffu, mx0, 1));
            mx0 = fmaxf(mx0, __shfl_xor_sync(0xffffffffu, mx0, 2));
            mx1 = fmaxf(mx1, __shfl_xor_sync(0xffffffffu, mx1, 1));
            mx1 = fmaxf(mx1, __shfl_xor_sync(0xffffffffu, mx1, 2));
            float mn0 = fmaxf(m0, mx0), mn1 = fmaxf(m1, mx1);
            float al0 = __expf(m0 - mn0), al1 = __expf(m1 - mn1);
            m0 = mn0; m1 = mn1;

            float sum0 = 0.f, sum1 = 0.f;
            uint32_t phA[8], phB[8], plA[8], plB[8];
#pragma unroll
            for (int nt = 0; nt < 8; ++nt) {
                float e0 = __expf(s4[nt][0] - mn0), e1 = __expf(s4[nt][1] - mn0);
                float e2 = __expf(s4[nt][2] - mn1), e3 = __expf(s4[nt][3] - mn1);
                sum0 += e0 + e1; sum1 += e2 + e3;
                __half2 h0 = __floats2half2_rn(e0, e1);
                __half2 h1 = __floats2half2_rn(e2, e3);
                float2 f0 = __half22float2(h0), f1 = __half22float2(h1);
                __half2 q0h = __floats2half2_rn(e0 - f0.x, e1 - f0.y);
                __half2 q1h = __floats2half2_rn(e2 - f1.x, e3 - f1.y);
                phA[nt] = *(uint32_t*)&h0;  phB[nt] = *(uint32_t*)&h1;
                plA[nt] = *(uint32_t*)&q0h; plB[nt] = *(uint32_t*)&q1h;
            }
            sum0 += __shfl_xor_sync(0xffffffffu, sum0, 1);
            sum0 += __shfl_xor_sync(0xffffffffu, sum0, 2);
            sum1 += __shfl_xor_sync(0xffffffffu, sum1, 1);
            sum1 += __shfl_xor_sync(0xffffffffu, sum1, 2);
            den0 = den0 * al0 + sum0;
            den1 = den1 * al1 + sum1;

#pragma unroll
            for (int nt = 0; nt < 16; ++nt) {
                o[nt][0] *= al0; o[nt][1] *= al0;
                o[nt][2] *= al1; o[nt][3] *= al1;
            }

#pragma unroll
            for (int ks = 0; ks < 4; ++ks) {
                uint32_t aH[4] = {phA[2*ks], phB[2*ks], phA[2*ks+1], phB[2*ks+1]};
                uint32_t aL[4] = {plA[2*ks], plB[2*ks], plA[2*ks+1], plB[2*ks+1]};
#pragma unroll
                for (int nj = 0; nj < 8; ++nj) {
                    int brow = brow0 + nj * 16;
                    int bch  = 2 * ks + bcbit;
                    uint32_t voff = (uint32_t)(brow * 8 + (bch ^ (brow & 7))) * 16;
                    uint32_t rH[4], rL[4];
                    LDSM_X4(rH, st + AVH_O + voff);
                    LDSM_X4(rL, st + AVL_O + voff);
                    uint32_t bH0[2] = {rH[0], rH[1]}, bH1[2] = {rH[2], rH[3]};
                    uint32_t bL0[2] = {rL[0], rL[1]}, bL1[2] = {rL[2], rL[3]};
                    MMA16816(o[2*nj],   aH, bH0);
                    MMA16816(o[2*nj+1], aH, bH1);
                    MMA16816(o[2*nj],   aH, bL0);
                    MMA16816(o[2*nj+1], aH, bL1);
                    MMA16816(o[2*nj],   aL, bH0);
                    MMA16816(o[2*nj+1], aL, bH1);
                }
            }
        }
        __syncthreads();
    }

    float inv0 = 1.f / den0, inv1 = 1.f / den1;
    int row0 = wq0 + g;
    float* O0 = Og + (size_t)(b*SEQ + row0) * DMODEL + h * DK;
    float* O1 = O0 + (size_t)8 * DMODEL;
#pragma unroll
    for (int nt = 0; nt < 16; ++nt) {
        int col = nt * 8 + 2 * t4;
        float2 v0 = {o[nt][0] * inv0, o[nt][1] * inv0};
        float2 v1 = {o[nt][2] * inv1, o[nt][3] * inv1};
        *(float2*)(O0 + col) = v0;
        *(float2*)(O1 + col) = v1;
    }
}

// ---------------------------------------------------------------------------
extern "C" void kernel_launch(void* const* d_in, const int* in_sizes, int n_in,
                              void* d_out, int out_size)
{
    (void)in_sizes; (void)n_in; (void)out_size;
    const float* x  = (const float*)d_in[0];
    const float* wq = (const float*)d_in[1];
    const float* wk = (const float*)d_in[2];
    const float* wv = (const float*)d_in[3];
    const float* wo = (const float*)d_in[4];
    const float* bo = (const float*)d_in[5];
    float* out = (float*)d_out;

    float *v, *ao;
    __half *x3, *ao3, *w3, *qh, *ql, *kh, *kl, *vth, *vtl;
    cudaGetSymbolAddress((void**)&v,   g_v);
    cudaGetSymbolAddress((void**)&ao,  g_ao);
    cudaGetSymbolAddress((void**)&x3,  g_x3);
    cudaGetSymbolAddress((void**)&ao3, g_ao3);
    cudaGetSymbolAddress((void**)&w3,  g_w3);
    cudaGetSymbolAddress((void**)&qh,  g_qh);
    cudaGetSymbolAddress((void**)&ql,  g_ql);
    cudaGetSymbolAddress((void**)&kh,  g_kh);
    cudaGetSymbolAddress((void**)&kl,  g_kl);
    cudaGetSymbolAddress((void**)&vth, g_vth);
    cudaGetSymbolAddress((void**)&vtl, g_vtl);

    const size_t W3SZ = (size_t)DMODEL * KX;

    conv_expand<<<(M_TOT*512)/256, 256>>>(x, x3, 1);
    conv_expand_w<<<dim3((DMODEL*512)/256, 4), 256>>>(wq, wk, wv, wo, w3);

    cudaFuncSetAttribute(gemm_mma, cudaFuncAttributeMaxDynamicSharedMemorySize,
                         (int)GEMM_SMEM);
    // fused QKV with rope+split epilogue: N = 6144
    dim3 gqkv(3*DMODEL/128, M_TOT/128);   // (48, 32)
    gemm_mma<<<gqkv, 256, GEMM_SMEM>>>(x3, w3, nullptr, nullptr,
                                       qh, ql, kh, kl, v, 1);

    vt_split<<<dim3(SEQ/64, BATCH*NHEADS), 256>>>(v, vth, vtl);

    cudaFuncSetAttribute(flash_attn_mma, cudaFuncAttributeMaxDynamicSharedMemorySize,
                         (int)ATTN_SMEM);
    dim3 agrid(SEQ/ABQ, BATCH*NHEADS);   // (16, 32)
    flash_attn_mma<<<agrid, 256, ATTN_SMEM>>>(qh, ql, kh, kl, vth, vtl, ao);

    conv_expand<<<(M_TOT*512)/256, 256>>>(ao, ao3, 1);
    dim3 gout(DMODEL/128, M_TOT/128);     // (16, 32)
    gemm_mma<<<gout, 256, GEMM_SMEM>>>(ao3, w3 + 3*W3SZ, bo, out,
                                       nullptr, nullptr, nullptr, nullptr,
                                       nullptr, 0);
}